// round 3
// baseline (speedup 1.0000x reference)
#include <cuda_runtime.h>

// Problem constants
#define D1     320
#define C_MAX  272
#define T_LEN  512

// Tiling
#define BM 64
#define BN 64
#define BK 16
#define TM 4
#define TN 4
#define NTHREADS 256

__global__ __launch_bounds__(NTHREADS)
void subject_conv_sgemm(const float* __restrict__ X,
                        const int*   __restrict__ subj,
                        const float* __restrict__ W,
                        float*       __restrict__ out)
{
    const int b  = blockIdx.z;
    const int m0 = blockIdx.y * BM;   // over D1 (5 tiles)
    const int n0 = blockIdx.x * BN;   // over T  (8 tiles)
    const int s  = subj[b];

    const float* A  = W + (size_t)s * D1 * C_MAX;       // [D1, C_MAX], row-major
    const float* Bm = X + (size_t)b * C_MAX * T_LEN;    // [C_MAX, T], row-major
    float*       O  = out + (size_t)b * D1 * T_LEN;

    __shared__ float As[BK][BM];   // transposed A tile: As[k][m]
    __shared__ float Bs[BK][BN];   // Bs[k][n]

    const int tid = threadIdx.x;
    const int tx  = tid & 15;       // 0..15 -> n micro
    const int ty  = tid >> 4;       // 0..15 -> m micro

    // A tile load mapping: 64 rows x 16 k -> 256 float4 (one per thread)
    const int a_row = tid >> 2;          // 0..63
    const int a_kc  = (tid & 3) * 4;     // 0,4,8,12
    // B tile load mapping: 16 k x 64 n -> 256 float4 (one per thread)
    const int b_k = tid >> 4;            // 0..15
    const int b_c = (tid & 15) * 4;      // 0..60

    float acc[TM][TN];
    #pragma unroll
    for (int i = 0; i < TM; i++)
        #pragma unroll
        for (int j = 0; j < TN; j++) acc[i][j] = 0.0f;

    const float* a_ptr = A + (m0 + a_row) * C_MAX + a_kc;
    const float* b_ptr = Bm + b_k * T_LEN + n0 + b_c;

    for (int k0 = 0; k0 < C_MAX; k0 += BK) {
        // --- Load tiles ---
        float4 av = *reinterpret_cast<const float4*>(a_ptr + k0);
        As[a_kc + 0][a_row] = av.x;
        As[a_kc + 1][a_row] = av.y;
        As[a_kc + 2][a_row] = av.z;
        As[a_kc + 3][a_row] = av.w;

        *reinterpret_cast<float4*>(&Bs[b_k][b_c]) =
            *reinterpret_cast<const float4*>(b_ptr + (size_t)k0 * T_LEN);

        __syncthreads();

        // --- Compute ---
        #pragma unroll
        for (int k = 0; k < BK; k++) {
            float4 a  = *reinterpret_cast<const float4*>(&As[k][ty * TM]);
            float4 bv = *reinterpret_cast<const float4*>(&Bs[k][tx * TN]);
            float am[TM] = {a.x, a.y, a.z, a.w};
            float bn[TN] = {bv.x, bv.y, bv.z, bv.w};
            #pragma unroll
            for (int i = 0; i < TM; i++)
                #pragma unroll
                for (int j = 0; j < TN; j++)
                    acc[i][j] = fmaf(am[i], bn[j], acc[i][j]);
        }

        __syncthreads();
    }

    // --- Store: each thread writes 4 rows x 1 float4 ---
    #pragma unroll
    for (int i = 0; i < TM; i++) {
        float4 o;
        o.x = acc[i][0]; o.y = acc[i][1]; o.z = acc[i][2]; o.w = acc[i][3];
        *reinterpret_cast<float4*>(O + (size_t)(m0 + ty * TM + i) * T_LEN + n0 + tx * TN) = o;
    }
}

extern "C" void kernel_launch(void* const* d_in, const int* in_sizes, int n_in,
                              void* d_out, int out_size)
{
    const float* X    = (const float*)d_in[0];  // [128, 272, 512] f32
    const int*   subj = (const int*)  d_in[1];  // [128] int32
    const float* W    = (const float*)d_in[2];  // [8, 320, 272] f32
    float*       out  = (float*)d_out;          // [128, 320, 512] f32

    dim3 grid(T_LEN / BN, D1 / BM, 128);   // (8, 5, 128)
    dim3 block(NTHREADS);
    subject_conv_sgemm<<<grid, block>>>(X, subj, W, out);
}

// round 5
// speedup vs baseline: 2.1323x; 2.1323x over previous
#include <cuda_runtime.h>
#include <cuda_fp16.h>
#include <cstdint>

// ---------------- Problem constants ----------------
#define B_SZ   128
#define D1     320
#define C_MAX  272
#define T_LEN  512

#define KPAD   288           // 9 stages of 32
#define NSTAGE 9
#define MTILES 3             // m0 in {0, 128, 192} (rows 192-255 duplicated, identical values)
#define NTILES 2             // 512 / 256

// Packed fragment scratch sizes
// X: per (b, nt): NSTAGE * 2(k16) * 32(n8) * 32(lane) * 8B  = 147456 B
#define XTILE_B   147456
// W: per (s, mt): NSTAGE * 2(k16) * 8(m16) * 32(lane) * 16B = 73728 B
#define WTILE_B   73728

__device__ __align__(128) unsigned char g_Xh[(size_t)B_SZ * NTILES * XTILE_B]; // ~36 MB
__device__ __align__(128) unsigned char g_Wh[(size_t)8 * MTILES * WTILE_B];    // ~1.7 MB

// ---------------- helpers ----------------
__device__ __forceinline__ uint32_t smem_u32(const void* p) {
    uint32_t a;
    asm("{ .reg .u64 t; cvta.to.shared.u64 t, %1; cvt.u32.u64 %0, t; }" : "=r"(a) : "l"(p));
    return a;
}

__device__ __forceinline__ uint32_t pack_h2(float lo, float hi) {
    __half2 h = __floats2half2_rn(lo, hi);   // .x = lo half (first k), .y = hi half
    return *reinterpret_cast<uint32_t*>(&h);
}

__device__ __forceinline__ void cp16(uint32_t dst, const void* src) {
    asm volatile("cp.async.cg.shared.global [%0], [%1], 16;" :: "r"(dst), "l"(src));
}
#define CP_COMMIT() asm volatile("cp.async.commit_group;" ::: "memory")
#define CP_WAIT(n)  asm volatile("cp.async.wait_group %0;" :: "n"(n) : "memory")

__device__ __forceinline__ void lds128(uint32_t* r, uint32_t addr) {
    asm volatile("ld.shared.v4.b32 {%0,%1,%2,%3}, [%4];"
                 : "=r"(r[0]), "=r"(r[1]), "=r"(r[2]), "=r"(r[3]) : "r"(addr));
}
__device__ __forceinline__ void lds64(uint32_t* r, uint32_t addr) {
    asm volatile("ld.shared.v2.b32 {%0,%1}, [%2];"
                 : "=r"(r[0]), "=r"(r[1]) : "r"(addr));
}

__device__ __forceinline__ void mma16816(float* c, const uint32_t* a, const uint32_t* b) {
    asm volatile(
        "mma.sync.aligned.m16n8k16.row.col.f32.f16.f16.f32 "
        "{%0,%1,%2,%3}, {%4,%5,%6,%7}, {%8,%9}, {%0,%1,%2,%3};"
        : "+f"(c[0]), "+f"(c[1]), "+f"(c[2]), "+f"(c[3])
        : "r"(a[0]), "r"(a[1]), "r"(a[2]), "r"(a[3]), "r"(b[0]), "r"(b[1]));
}

// ---------------- Prep X: f32 [b][c][t] -> fp16 B-fragments ----------------
// Slot i (per (b,nt)): lane = i&31, n8 = (i>>5)&31, k16 = (i>>10)&1, ks = i>>11.
// n_local = n8*8 + lane/4 ; kbase = ks*32 + k16*16 + (lane&3)*2
// slot holds b0 = h2(X[kbase], X[kbase+1]), b1 = h2(X[kbase+8], X[kbase+9]) at column n.
__global__ __launch_bounds__(256) void prep_x(const float* __restrict__ X) {
    const int nt = blockIdx.x, b = blockIdx.y;
    const float* xb = X + (size_t)b * C_MAX * T_LEN + nt * 256;
    uint2* dst = (uint2*)(g_Xh + ((size_t)b * NTILES + nt) * XTILE_B);

    const int NSLOT = NSTAGE * 2 * 32 * 32;  // 18432
    for (int i = threadIdx.x; i < NSLOT; i += 256) {
        const int lane = i & 31;
        const int n8   = (i >> 5) & 31;
        const int k16  = (i >> 10) & 1;
        const int ks   = i >> 11;
        const int n    = n8 * 8 + (lane >> 2);
        const int k0   = ks * 32 + k16 * 16 + (lane & 3) * 2;

        float v0 = (k0     < C_MAX) ? xb[(size_t)(k0    ) * T_LEN + n] : 0.0f;
        float v1 = (k0 + 1 < C_MAX) ? xb[(size_t)(k0 + 1) * T_LEN + n] : 0.0f;
        float v2 = (k0 + 8 < C_MAX) ? xb[(size_t)(k0 + 8) * T_LEN + n] : 0.0f;
        float v3 = (k0 + 9 < C_MAX) ? xb[(size_t)(k0 + 9) * T_LEN + n] : 0.0f;

        uint2 o;
        o.x = pack_h2(v0, v1);   // b0
        o.y = pack_h2(v2, v3);   // b1
        dst[i] = o;
    }
}

// ---------------- Prep W: f32 [s][d][c] -> fp16 A-fragments ----------------
// Slot i (per (s,mt)): lane = i&31, m16 = (i>>5)&7, k16 = (i>>8)&1, ks = i>>9.
// g = lane/4, c2 = lane&3; regs r0..r3: m += (r&1)*8, k += (r>>1)*8.
__global__ __launch_bounds__(256) void prep_w(const float* __restrict__ W) {
    const int mt = blockIdx.x, s = blockIdx.y;
    const int m0 = (mt < 2) ? mt * 128 : 192;
    const float* ws = W + (size_t)s * D1 * C_MAX;
    uint4* dst = (uint4*)(g_Wh + ((size_t)s * MTILES + mt) * WTILE_B);

    const int NSLOT = NSTAGE * 2 * 8 * 32;   // 4608
    for (int i = threadIdx.x; i < NSLOT; i += 256) {
        const int lane = i & 31;
        const int m16  = (i >> 5) & 7;
        const int k16  = (i >> 8) & 1;
        const int ks   = i >> 9;
        const int g    = lane >> 2;
        const int k0   = ks * 32 + k16 * 16 + (lane & 3) * 2;
        const int mA   = m0 + m16 * 16 + g;

        uint32_t r[4];
        #pragma unroll
        for (int rr = 0; rr < 4; rr++) {
            const int m = mA + (rr & 1) * 8;
            const int k = k0 + (rr >> 1) * 8;
            float v0 = (k     < C_MAX) ? ws[(size_t)m * C_MAX + k    ] : 0.0f;
            float v1 = (k + 1 < C_MAX) ? ws[(size_t)m * C_MAX + k + 1] : 0.0f;
            r[rr] = pack_h2(v0, v1);
        }
        uint4 o; o.x = r[0]; o.y = r[1]; o.z = r[2]; o.w = r[3];
        dst[i] = o;
    }
}

// ---------------- GEMM: 128m x 256n CTA, 512 threads, fp16 HMMA ----------------
// smem: bufA [2][8192] at 0, bufB [2][16384] at 16384.  total 49152 B
#define SM_A(stage)  ((stage) * 8192)
#define SM_B(stage)  (16384 + (stage) * 16384)
#define GEMM_SMEM    49152

__global__ __launch_bounds__(512) void gemm_hmma(const int* __restrict__ subj,
                                                 float* __restrict__ out) {
    extern __shared__ unsigned char dsm[];
    const uint32_t sbase = smem_u32(dsm);

    const int tid  = threadIdx.x;
    const int lane = tid & 31;
    const int wid  = tid >> 5;          // 0..15
    const int wm   = wid & 3;           // 4 m-warps  (m16 idx 2*wm, 2*wm+1)
    const int wn   = wid >> 2;          // 4 n-warps  (n8 idx 8*wn .. +7)

    const int nt = blockIdx.x, mt = blockIdx.y, b = blockIdx.z;
    const int s  = subj[b];
    const int m0 = (mt < 2) ? mt * 128 : 192;

    const unsigned char* srcA = g_Wh + ((size_t)s * MTILES + mt) * WTILE_B;
    const unsigned char* srcB = g_Xh + ((size_t)b * NTILES + nt) * XTILE_B;

    float acc[2][8][4];
    #pragma unroll
    for (int i = 0; i < 2; i++)
        #pragma unroll
        for (int j = 0; j < 8; j++)
            #pragma unroll
            for (int q = 0; q < 4; q++) acc[i][j][q] = 0.0f;

    // ---- stage copy: A 8KB (1x16B/thread), B 16KB (2x16B/thread) ----
    auto copy_stage = [&](int ks) {
        const int buf = ks & 1;
        cp16(sbase + SM_A(buf) + tid * 16, srcA + (size_t)ks * 8192 + tid * 16);
        cp16(sbase + SM_B(buf) + tid * 16,        srcB + (size_t)ks * 16384 + tid * 16);
        cp16(sbase + SM_B(buf) + 8192 + tid * 16, srcB + (size_t)ks * 16384 + 8192 + tid * 16);
    };

    copy_stage(0);
    CP_COMMIT();

    for (int ks = 0; ks < NSTAGE; ks++) {
        if (ks < NSTAGE - 1) {
            copy_stage(ks + 1);
            CP_COMMIT();
            CP_WAIT(1);
        } else {
            CP_WAIT(0);
        }
        __syncthreads();

        const uint32_t aB = sbase + SM_A(ks & 1);
        const uint32_t bB = sbase + SM_B(ks & 1);

        #pragma unroll
        for (int k16 = 0; k16 < 2; k16++) {
            uint32_t afr[2][4];
            #pragma unroll
            for (int mi = 0; mi < 2; mi++)
                lds128(afr[mi], aB + k16 * 4096 + (2 * wm + mi) * 512 + lane * 16);

            uint32_t bfr[8][2];
            #pragma unroll
            for (int ni = 0; ni < 8; ni++)
                lds64(bfr[ni], bB + k16 * 8192 + (8 * wn + ni) * 256 + lane * 8);

            #pragma unroll
            for (int mi = 0; mi < 2; mi++)
                #pragma unroll
                for (int ni = 0; ni < 8; ni++)
                    mma16816(acc[mi][ni], afr[mi], bfr[ni]);
        }
        __syncthreads();
    }

    // ---- epilogue: registers -> gmem (float2 stores) ----
    const int g  = lane >> 2;
    const int c2 = (lane & 3) * 2;
    const int col0 = nt * 256 + wn * 64 + c2;
    #pragma unroll
    for (int mi = 0; mi < 2; mi++) {
        const int row = m0 + wm * 32 + mi * 16 + g;
        float* o0 = out + ((size_t)b * D1 + row) * T_LEN + col0;
        float* o1 = out + ((size_t)b * D1 + row + 8) * T_LEN + col0;
        #pragma unroll
        for (int ni = 0; ni < 8; ni++) {
            float2 v0; v0.x = acc[mi][ni][0]; v0.y = acc[mi][ni][1];
            float2 v1; v1.x = acc[mi][ni][2]; v1.y = acc[mi][ni][3];
            *(float2*)(o0 + ni * 8) = v0;
            *(float2*)(o1 + ni * 8) = v1;
        }
    }
}

// ---------------- Host launcher ----------------
extern "C" void kernel_launch(void* const* d_in, const int* in_sizes, int n_in,
                              void* d_out, int out_size) {
    const float* X    = (const float*)d_in[0];  // [128, 272, 512]
    const int*   subj = (const int*)  d_in[1];  // [128]
    const float* W    = (const float*)d_in[2];  // [8, 320, 272]
    float*       out  = (float*)d_out;          // [128, 320, 512]

    prep_w<<<dim3(MTILES, 8),    256>>>(W);
    prep_x<<<dim3(NTILES, B_SZ), 256>>>(X);
    gemm_hmma<<<dim3(NTILES, MTILES, B_SZ), 512, GEMM_SMEM>>>(subj, out);
}

// round 7
// speedup vs baseline: 4.0712x; 1.9093x over previous
#include <cuda_runtime.h>
#include <cuda_fp16.h>
#include <cstdint>

// ---------------- Problem constants ----------------
#define B_SZ   128
#define D1     320
#define C_MAX  272
#define T_LEN  512

#define NSTAGE 9            // K padded to 288 = 9 * 32
#define MTILES 3            // m0 in {0, 128, 192} (overlap rows identical -> deterministic)
#define NTILES 4            // 512 / 128

// Fragment scratch: per (b,nt,ks): 2 k16 * 16 n8 * 32 lanes * 8B  = 8192 B
// per (s,mt,ks): 2 k16 * 8 m16 * 32 lanes * 16B = 8192 B
#define STAGE_B 8192
#define XTILE_B (NSTAGE * STAGE_B)   // 73728 per (b,nt)
#define WTILE_B (NSTAGE * STAGE_B)   // 73728 per (s,mt)

__device__ __align__(128) unsigned char g_Xh[(size_t)B_SZ * NTILES * XTILE_B]; // ~37.7 MB
__device__ __align__(128) unsigned char g_Wh[(size_t)8 * MTILES * WTILE_B];    // ~1.7 MB

// ---------------- helpers ----------------
__device__ __forceinline__ uint32_t smem_u32(const void* p) {
    uint32_t a;
    asm("{ .reg .u64 t; cvta.to.shared.u64 t, %1; cvt.u32.u64 %0, t; }" : "=r"(a) : "l"(p));
    return a;
}
__device__ __forceinline__ uint32_t pack_h2(float lo, float hi) {
    __half2 h = __floats2half2_rn(lo, hi);
    return *reinterpret_cast<uint32_t*>(&h);
}
__device__ __forceinline__ void cp16(uint32_t dst, const void* src) {
    asm volatile("cp.async.cg.shared.global [%0], [%1], 16;" :: "r"(dst), "l"(src));
}
#define CP_COMMIT() asm volatile("cp.async.commit_group;" ::: "memory")
#define CP_WAIT(n)  asm volatile("cp.async.wait_group %0;" :: "n"(n) : "memory")

__device__ __forceinline__ void lds128(uint32_t* r, uint32_t addr) {
    asm volatile("ld.shared.v4.b32 {%0,%1,%2,%3}, [%4];"
                 : "=r"(r[0]), "=r"(r[1]), "=r"(r[2]), "=r"(r[3]) : "r"(addr));
}
__device__ __forceinline__ void lds64(uint32_t* r, uint32_t addr) {
    asm volatile("ld.shared.v2.b32 {%0,%1}, [%2];"
                 : "=r"(r[0]), "=r"(r[1]) : "r"(addr));
}
__device__ __forceinline__ void mma16816(float* c, const uint32_t* a, const uint32_t* b) {
    asm volatile(
        "mma.sync.aligned.m16n8k16.row.col.f32.f16.f16.f32 "
        "{%0,%1,%2,%3}, {%4,%5,%6,%7}, {%8,%9}, {%0,%1,%2,%3};"
        : "+f"(c[0]), "+f"(c[1]), "+f"(c[2]), "+f"(c[3])
        : "r"(a[0]), "r"(a[1]), "r"(a[2]), "r"(a[3]), "r"(b[0]), "r"(b[1]));
}

// ---------------- Prep X: coalesced slab transpose -> fp16 B-fragments ----------------
// Block (ks, nt, b): loads X slab [32 c x 128 t] into padded smem (coalesced),
// emits 1024 uint2 fragment slots, layout: slot j = k16*512 + n8*32 + lane.
//   t  = n8*8 + (lane>>2);  kc = k16*16 + (lane&3)*2
//   val = { h2(X[kc],X[kc+1]), h2(X[kc+8],X[kc+9]) } at column t.
__global__ __launch_bounds__(256) void prep_x(const float* __restrict__ X) {
    const int ks = blockIdx.x, nt = blockIdx.y, b = blockIdx.z;
    __shared__ float slab[32][132];   // padded: stride 132 kills quad bank conflicts

    const int tid = threadIdx.x;
    const int c0 = ks * 32;
    const float* xb = X + (size_t)b * C_MAX * T_LEN + (size_t)nt * 128;

    // Load 32x128 floats: 1024 float4, 4 per thread, rows coalesced.
    #pragma unroll
    for (int it = 0; it < 4; it++) {
        const int idx = tid + it * 256;        // 0..1023
        const int cl  = idx >> 5;              // 0..31
        const int t4  = (idx & 31) * 4;
        float4 v = make_float4(0.f, 0.f, 0.f, 0.f);
        if (c0 + cl < C_MAX)
            v = *(const float4*)(xb + (size_t)(c0 + cl) * T_LEN + t4);
        slab[cl][t4 + 0] = v.x; slab[cl][t4 + 1] = v.y;
        slab[cl][t4 + 2] = v.z; slab[cl][t4 + 3] = v.w;
    }
    __syncthreads();

    uint2* dst = (uint2*)(g_Xh + (((size_t)b * NTILES + nt) * NSTAGE + ks) * STAGE_B);
    #pragma unroll
    for (int it = 0; it < 4; it++) {
        const int j    = tid + it * 256;       // 0..1023
        const int lane = j & 31;
        const int n8   = (j >> 5) & 15;
        const int k16  = j >> 9;
        const int t    = n8 * 8 + (lane >> 2);
        const int kc   = k16 * 16 + (lane & 3) * 2;
        uint2 o;
        o.x = pack_h2(slab[kc][t],     slab[kc + 1][t]);
        o.y = pack_h2(slab[kc + 8][t], slab[kc + 9][t]);
        dst[j] = o;
    }
}

// ---------------- Prep W: fp16 A-fragments ----------------
// Block (ks, mt, s): 512 uint4 slots, layout: slot j = k16*256 + m16*32 + lane.
//   m = m0 + m16*16 + lane>>2; k0 = ks*32 + k16*16 + (lane&3)*2
//   regs r0..r3: m += (rr&1)*8, k += (rr>>1)*8
__global__ __launch_bounds__(128) void prep_w(const float* __restrict__ W) {
    const int ks = blockIdx.x, mt = blockIdx.y, s = blockIdx.z;
    const int m0 = (mt < 2) ? mt * 128 : 192;
    const float* ws = W + (size_t)s * D1 * C_MAX;
    uint4* dst = (uint4*)(g_Wh + (((size_t)s * MTILES + mt) * NSTAGE + ks) * STAGE_B);

    const int tid = threadIdx.x;
    #pragma unroll
    for (int it = 0; it < 4; it++) {
        const int j    = tid + it * 128;       // 0..511
        const int lane = j & 31;
        const int m16  = (j >> 5) & 7;
        const int k16  = j >> 8;
        const int g    = lane >> 2;
        const int k0   = ks * 32 + k16 * 16 + (lane & 3) * 2;
        const int mA   = m0 + m16 * 16 + g;

        uint32_t r[4];
        #pragma unroll
        for (int rr = 0; rr < 4; rr++) {
            const int m = mA + (rr & 1) * 8;
            const int k = k0 + (rr >> 1) * 8;
            float v0 = (k     < C_MAX) ? ws[(size_t)m * C_MAX + k    ] : 0.0f;
            float v1 = (k + 1 < C_MAX) ? ws[(size_t)m * C_MAX + k + 1] : 0.0f;
            r[rr] = pack_h2(v0, v1);
        }
        uint4 o; o.x = r[0]; o.y = r[1]; o.z = r[2]; o.w = r[3];
        dst[j] = o;
    }
}

// ---------------- GEMM: 128m x 128n CTA, 256 threads, 3-stage cp.async ----------------
// smem per stage: A 8KB + B 8KB = 16KB; 3 stages = 48KB (no opt-in needed).
#define STG_SM   16384
#define GEMM_SMEM (3 * STG_SM)

__global__ __launch_bounds__(256, 2) void gemm_hmma(const int* __restrict__ subj,
                                                    float* __restrict__ out) {
    extern __shared__ unsigned char dsm[];
    const uint32_t sbase = smem_u32(dsm);

    const int tid  = threadIdx.x;
    const int lane = tid & 31;
    const int wid  = tid >> 5;          // 0..7
    const int wm   = wid & 3;           // 4 m-warps: m16 {2wm, 2wm+1}
    const int wn   = wid >> 2;          // 2 n-warps: n8 {8wn .. 8wn+7}

    const int nt = blockIdx.x, mt = blockIdx.y, b = blockIdx.z;
    const int s  = subj[b];
    const int m0 = (mt < 2) ? mt * 128 : 192;

    const unsigned char* srcA = g_Wh + ((size_t)s * MTILES + mt) * WTILE_B;
    const unsigned char* srcB = g_Xh + ((size_t)b * NTILES + nt) * XTILE_B;

    float acc[2][8][4];
    #pragma unroll
    for (int i = 0; i < 2; i++)
        #pragma unroll
        for (int j = 0; j < 8; j++)
            #pragma unroll
            for (int q = 0; q < 4; q++) acc[i][j][q] = 0.0f;

    // Stage copy: 16KB with 256 threads -> 4 cp16/thread.
    auto copy_stage = [&](int ks) {
        const uint32_t d = sbase + (uint32_t)(ks % 3) * STG_SM;
        const unsigned char* a = srcA + (size_t)ks * STAGE_B;
        const unsigned char* bb = srcB + (size_t)ks * STAGE_B;
        cp16(d + tid * 16,        a  + tid * 16);
        cp16(d + 4096 + tid * 16, a  + 4096 + tid * 16);
        cp16(d + 8192 + tid * 16,        bb + tid * 16);
        cp16(d + 12288 + tid * 16,       bb + 4096 + tid * 16);
    };

    copy_stage(0); CP_COMMIT();
    copy_stage(1); CP_COMMIT();

    #pragma unroll 1
    for (int ks = 0; ks < NSTAGE; ks++) {
        if (ks == NSTAGE - 1) { CP_WAIT(0); } else { CP_WAIT(1); }
        __syncthreads();
        if (ks + 2 < NSTAGE) { copy_stage(ks + 2); CP_COMMIT(); }

        const uint32_t stg = sbase + (uint32_t)(ks % 3) * STG_SM;
        const uint32_t aB = stg;
        const uint32_t bB = stg + 8192;

        #pragma unroll
        for (int k16 = 0; k16 < 2; k16++) {
            uint32_t afr[2][4];
            #pragma unroll
            for (int mi = 0; mi < 2; mi++)
                lds128(afr[mi], aB + k16 * 4096 + (2 * wm + mi) * 512 + lane * 16);

            uint32_t bfr[8][2];
            #pragma unroll
            for (int ni = 0; ni < 8; ni++)
                lds64(bfr[ni], bB + k16 * 4096 + (8 * wn + ni) * 256 + lane * 8);

            #pragma unroll
            for (int mi = 0; mi < 2; mi++)
                #pragma unroll
                for (int ni = 0; ni < 8; ni++)
                    mma16816(acc[mi][ni], afr[mi], bfr[ni]);
        }
    }

    // ---- epilogue: registers -> gmem ----
    const int g  = lane >> 2;
    const int c2 = (lane & 3) * 2;
    const int col0 = nt * 128 + wn * 64 + c2;
    #pragma unroll
    for (int mi = 0; mi < 2; mi++) {
        const int row = m0 + wm * 32 + mi * 16 + g;
        float* o0 = out + ((size_t)b * D1 + row) * T_LEN + col0;
        float* o1 = out + ((size_t)b * D1 + row + 8) * T_LEN + col0;
        #pragma unroll
        for (int ni = 0; ni < 8; ni++) {
            float2 v0; v0.x = acc[mi][ni][0]; v0.y = acc[mi][ni][1];
            float2 v1; v1.x = acc[mi][ni][2]; v1.y = acc[mi][ni][3];
            *(float2*)(o0 + ni * 8) = v0;
            *(float2*)(o1 + ni * 8) = v1;
        }
    }
}

// ---------------- Host launcher ----------------
extern "C" void kernel_launch(void* const* d_in, const int* in_sizes, int n_in,
                              void* d_out, int out_size) {
    const float* X    = (const float*)d_in[0];  // [128, 272, 512]
    const int*   subj = (const int*)  d_in[1];  // [128]
    const float* W    = (const float*)d_in[2];  // [8, 320, 272]
    float*       out  = (float*)d_out;          // [128, 320, 512]

    prep_w<<<dim3(NSTAGE, MTILES, 8),     128>>>(W);
    prep_x<<<dim3(NSTAGE, NTILES, B_SZ),  256>>>(X);
    gemm_hmma<<<dim3(NTILES, MTILES, B_SZ), 256, GEMM_SMEM>>>(subj, out);
}

// round 8
// speedup vs baseline: 4.6084x; 1.1320x over previous
#include <cuda_runtime.h>
#include <cuda_fp16.h>
#include <cstdint>

// ---------------- Problem constants ----------------
#define B_SZ   128
#define D1     320
#define C_MAX  272
#define T_LEN  512

#define NSTAGE 9            // K covered by 9 stages of 32 (last stage: only 16 real k)
#define NTILES 4            // 512 / 128

// X fragments: per (b,nt,ks): 2 k16 * 16 n8 * 32 lanes * 8B = 8192 B
#define STAGE_B 8192
#define XTILE_B (NSTAGE * STAGE_B)          // 73728 per (b,nt)
// W fragments: per (s,ks): 20 m16 * 2 k16 * 32 lanes * 16B = 20480 B (contiguous m16)
#define WSTAGE_B 20480

__device__ __align__(128) unsigned char g_Xh[(size_t)B_SZ * NTILES * XTILE_B]; // ~37.7 MB
__device__ __align__(128) unsigned char g_Wh[(size_t)8 * NSTAGE * WSTAGE_B];   // ~1.5 MB

// ---------------- helpers ----------------
__device__ __forceinline__ uint32_t smem_u32(const void* p) {
    uint32_t a;
    asm("{ .reg .u64 t; cvta.to.shared.u64 t, %1; cvt.u32.u64 %0, t; }" : "=r"(a) : "l"(p));
    return a;
}
__device__ __forceinline__ uint32_t pack_h2(float lo, float hi) {
    __half2 h = __floats2half2_rn(lo, hi);
    return *reinterpret_cast<uint32_t*>(&h);
}
__device__ __forceinline__ void cp16(uint32_t dst, const void* src) {
    asm volatile("cp.async.cg.shared.global [%0], [%1], 16;" :: "r"(dst), "l"(src));
}
#define CP_COMMIT() asm volatile("cp.async.commit_group;" ::: "memory")
#define CP_WAIT(n)  asm volatile("cp.async.wait_group %0;" :: "n"(n) : "memory")

__device__ __forceinline__ void lds128(uint32_t* r, uint32_t addr) {
    asm volatile("ld.shared.v4.b32 {%0,%1,%2,%3}, [%4];"
                 : "=r"(r[0]), "=r"(r[1]), "=r"(r[2]), "=r"(r[3]) : "r"(addr));
}
__device__ __forceinline__ void lds64(uint32_t* r, uint32_t addr) {
    asm volatile("ld.shared.v2.b32 {%0,%1}, [%2];"
                 : "=r"(r[0]), "=r"(r[1]) : "r"(addr));
}
__device__ __forceinline__ void mma16816(float* c, const uint32_t* a, const uint32_t* b) {
    asm volatile(
        "mma.sync.aligned.m16n8k16.row.col.f32.f16.f16.f32 "
        "{%0,%1,%2,%3}, {%4,%5,%6,%7}, {%8,%9}, {%0,%1,%2,%3};"
        : "+f"(c[0]), "+f"(c[1]), "+f"(c[2]), "+f"(c[3])
        : "r"(a[0]), "r"(a[1]), "r"(a[2]), "r"(a[3]), "r"(b[0]), "r"(b[1]));
}

// ---------------- Fused prep: X fragments always; W fragments on a subset ----------------
// X part (block ks,nt,b): slab transpose [32c x 128t] -> 1024 uint2 slots,
// slot j = k16*512 + n8*32 + lane; t = n8*8 + lane/4; kc = k16*16 + (lane&3)*2.
// W part (blocks nt==0 && b<8, s=b): 1280 uint4 slots, slot j = (m16*2+k16)*32+lane.
__global__ __launch_bounds__(256) void prep_all(const float* __restrict__ X,
                                                const float* __restrict__ W) {
    const int ks = blockIdx.x, nt = blockIdx.y, b = blockIdx.z;
    __shared__ float slab[32][132];   // padded stride kills quad bank conflicts

    const int tid = threadIdx.x;
    const int c0 = ks * 32;
    const float* xb = X + (size_t)b * C_MAX * T_LEN + (size_t)nt * 128;

    #pragma unroll
    for (int it = 0; it < 4; it++) {
        const int idx = tid + it * 256;        // 0..1023
        const int cl  = idx >> 5;              // 0..31
        const int t4  = (idx & 31) * 4;
        float4 v = make_float4(0.f, 0.f, 0.f, 0.f);
        if (c0 + cl < C_MAX)
            v = *(const float4*)(xb + (size_t)(c0 + cl) * T_LEN + t4);
        slab[cl][t4 + 0] = v.x; slab[cl][t4 + 1] = v.y;
        slab[cl][t4 + 2] = v.z; slab[cl][t4 + 3] = v.w;
    }
    __syncthreads();

    uint2* dst = (uint2*)(g_Xh + (((size_t)b * NTILES + nt) * NSTAGE + ks) * STAGE_B);
    #pragma unroll
    for (int it = 0; it < 4; it++) {
        const int j    = tid + it * 256;       // 0..1023
        const int lane = j & 31;
        const int n8   = (j >> 5) & 15;
        const int k16  = j >> 9;
        const int t    = n8 * 8 + (lane >> 2);
        const int kc   = k16 * 16 + (lane & 3) * 2;
        uint2 o;
        o.x = pack_h2(slab[kc][t],     slab[kc + 1][t]);
        o.y = pack_h2(slab[kc + 8][t], slab[kc + 9][t]);
        dst[j] = o;
    }

    // ---- W fragments (72 blocks total) ----
    if (nt == 0 && b < 8) {
        const int s = b;
        const float* ws = W + (size_t)s * D1 * C_MAX;
        uint4* wd = (uint4*)(g_Wh + ((size_t)s * NSTAGE + ks) * WSTAGE_B);
        #pragma unroll
        for (int it = 0; it < 5; it++) {
            const int j = tid + it * 256;      // 0..1279
            const int lane = j & 31;
            const int k16  = (j >> 5) & 1;
            const int m16  = j >> 6;           // 0..19
            const int g    = lane >> 2;
            const int k0   = ks * 32 + k16 * 16 + (lane & 3) * 2;
            const int mA   = m16 * 16 + g;     // < 320 always

            uint32_t r[4];
            #pragma unroll
            for (int rr = 0; rr < 4; rr++) {
                const int m = mA + (rr & 1) * 8;
                const int k = k0 + (rr >> 1) * 8;
                float v0 = (k     < C_MAX) ? ws[(size_t)m * C_MAX + k    ] : 0.0f;
                float v1 = (k + 1 < C_MAX) ? ws[(size_t)m * C_MAX + k + 1] : 0.0f;
                r[rr] = pack_h2(v0, v1);
            }
            uint4 o; o.x = r[0]; o.y = r[1]; o.z = r[2]; o.w = r[3];
            wd[j] = o;
        }
    }
}

// ---------------- GEMM: templated on m16-count (8 -> 128 rows, 4 -> 64 rows) ----------------
// smem stage: A (up to 8KB, layout [m16][k16][lane*16B]) at 0, B (8KB) at 8192.
#define STG_SM    16384
#define GEMM_SMEM (3 * STG_SM)

template <int MCNT>   // m16 tiles per CTA: 8 (full) or 4 (small)
__global__ __launch_bounds__(256, 2) void gemm_hmma(const int* __restrict__ subj,
                                                    float* __restrict__ out) {
    constexpr int MW   = MCNT / 2;    // m-warp groups (each owns 2 m16)
    constexpr int NWRP = 8 / MW;      // n-warp groups
    constexpr int N8W  = 16 / NWRP;   // n8 per warp

    extern __shared__ unsigned char dsm[];
    const uint32_t sbase = smem_u32(dsm);

    const int tid  = threadIdx.x;
    const int lane = tid & 31;
    const int wid  = tid >> 5;
    const int wm   = wid % MW;
    const int wn   = wid / MW;

    const int nt = blockIdx.x, b = blockIdx.z;
    const int m16base = (MCNT == 8) ? blockIdx.y * 8 : 16;
    const int s  = subj[b];

    const unsigned char* srcA = g_Wh + (size_t)s * NSTAGE * WSTAGE_B + (size_t)m16base * 1024;
    const unsigned char* srcB = g_Xh + ((size_t)b * NTILES + nt) * XTILE_B;

    float acc[2][N8W][4];
    #pragma unroll
    for (int i = 0; i < 2; i++)
        #pragma unroll
        for (int j = 0; j < N8W; j++)
            #pragma unroll
            for (int q = 0; q < 4; q++) acc[i][j][q] = 0.0f;

    auto copy_stage = [&](int ks) {
        const uint32_t d = sbase + (uint32_t)(ks % 3) * STG_SM;
        const unsigned char* a  = srcA + (size_t)ks * WSTAGE_B;
        const unsigned char* bb = srcB + (size_t)ks * STAGE_B;
        cp16(d + tid * 16, a + tid * 16);
        if (MCNT == 8) cp16(d + 4096 + tid * 16, a + 4096 + tid * 16);
        cp16(d + 8192 + tid * 16,  bb + tid * 16);
        cp16(d + 12288 + tid * 16, bb + 4096 + tid * 16);
    };

    copy_stage(0); CP_COMMIT();
    copy_stage(1); CP_COMMIT();

    #pragma unroll 1
    for (int ks = 0; ks < NSTAGE; ks++) {
        if (ks == NSTAGE - 1) { CP_WAIT(0); } else { CP_WAIT(1); }
        __syncthreads();
        if (ks + 2 < NSTAGE) { copy_stage(ks + 2); CP_COMMIT(); }

        const uint32_t stg = sbase + (uint32_t)(ks % 3) * STG_SM;
        const uint32_t aB = stg;
        const uint32_t bB = stg + 8192;

        #pragma unroll
        for (int k16 = 0; k16 < 2; k16++) {
            if (k16 == 1 && ks == NSTAGE - 1) break;   // K=272: last stage is half

            uint32_t afr[2][4];
            #pragma unroll
            for (int mi = 0; mi < 2; mi++)
                lds128(afr[mi], aB + (uint32_t)(((2 * wm + mi) * 2 + k16) * 512) + lane * 16);

            uint32_t bfr[N8W][2];
            #pragma unroll
            for (int ni = 0; ni < N8W; ni++)
                lds64(bfr[ni], bB + (uint32_t)(k16 * 4096 + (wn * N8W + ni) * 256) + lane * 8);

            #pragma unroll
            for (int mi = 0; mi < 2; mi++)
                #pragma unroll
                for (int ni = 0; ni < N8W; ni++)
                    mma16816(acc[mi][ni], afr[mi], bfr[ni]);
        }
    }

    // ---- epilogue ----
    const int g  = lane >> 2;
    const int c2 = (lane & 3) * 2;
    const int col0 = nt * 128 + wn * (N8W * 8) + c2;
    #pragma unroll
    for (int mi = 0; mi < 2; mi++) {
        const int row = m16base * 16 + wm * 32 + mi * 16 + g;
        float* o0 = out + ((size_t)b * D1 + row) * T_LEN + col0;
        float* o1 = out + ((size_t)b * D1 + row + 8) * T_LEN + col0;
        #pragma unroll
        for (int ni = 0; ni < N8W; ni++) {
            float2 v0; v0.x = acc[mi][ni][0]; v0.y = acc[mi][ni][1];
            float2 v1; v1.x = acc[mi][ni][2]; v1.y = acc[mi][ni][3];
            *(float2*)(o0 + ni * 8) = v0;
            *(float2*)(o1 + ni * 8) = v1;
        }
    }
}

// ---------------- Host launcher ----------------
extern "C" void kernel_launch(void* const* d_in, const int* in_sizes, int n_in,
                              void* d_out, int out_size) {
    const float* X    = (const float*)d_in[0];  // [128, 272, 512]
    const int*   subj = (const int*)  d_in[1];  // [128]
    const float* W    = (const float*)d_in[2];  // [8, 320, 272]
    float*       out  = (float*)d_out;          // [128, 320, 512]

    prep_all<<<dim3(NSTAGE, NTILES, B_SZ), 256>>>(X, W);
    gemm_hmma<8><<<dim3(NTILES, 2, B_SZ), 256, GEMM_SMEM>>>(subj, out);  // rows 0..255
    gemm_hmma<4><<<dim3(NTILES, 1, B_SZ), 256, GEMM_SMEM>>>(subj, out);  // rows 256..319
}

// round 9
// speedup vs baseline: 4.6351x; 1.0058x over previous
#include <cuda_runtime.h>
#include <cuda_fp16.h>
#include <cstdint>

// ---------------- Problem constants ----------------
#define B_SZ   128
#define D1     320
#define C_MAX  272
#define T_LEN  512

#define NSTAGE 9            // K covered by 9 stages of 32 (last stage: only 16 real k)
#define NTILES 4            // 512 / 128

// W fragments: per (s,ks): 20 m16 * 2 k16 * 32 lanes * 16B = 20480 B
#define WSTAGE_B 20480
__device__ __align__(128) unsigned char g_Wh[(size_t)8 * NSTAGE * WSTAGE_B];   // ~1.5 MB

// ---------------- helpers ----------------
__device__ __forceinline__ uint32_t smem_u32(const void* p) {
    uint32_t a;
    asm("{ .reg .u64 t; cvta.to.shared.u64 t, %1; cvt.u32.u64 %0, t; }" : "=r"(a) : "l"(p));
    return a;
}
__device__ __forceinline__ uint32_t pack_h2(float lo, float hi) {
    __half2 h = __floats2half2_rn(lo, hi);
    return *reinterpret_cast<uint32_t*>(&h);
}
// cp.async with src-size predicate (0 bytes -> zero-fill)
__device__ __forceinline__ void cp16p(uint32_t dst, const void* src, int bytes) {
    asm volatile("cp.async.cg.shared.global [%0], [%1], 16, %2;"
                 :: "r"(dst), "l"(src), "r"(bytes));
}
#define CP_COMMIT() asm volatile("cp.async.commit_group;" ::: "memory")
#define CP_WAIT(n)  asm volatile("cp.async.wait_group %0;" :: "n"(n) : "memory")

__device__ __forceinline__ void ldg128(uint32_t* r, const void* p) {
    asm volatile("ld.global.nc.v4.b32 {%0,%1,%2,%3}, [%4];"
                 : "=r"(r[0]), "=r"(r[1]), "=r"(r[2]), "=r"(r[3]) : "l"(p));
}
__device__ __forceinline__ void lds64(uint32_t* r, uint32_t addr) {
    asm volatile("ld.shared.v2.b32 {%0,%1}, [%2];"
                 : "=r"(r[0]), "=r"(r[1]) : "r"(addr));
}
__device__ __forceinline__ void sts64(uint32_t addr, uint32_t v0, uint32_t v1) {
    asm volatile("st.shared.v2.b32 [%0], {%1,%2};" :: "r"(addr), "r"(v0), "r"(v1) : "memory");
}
__device__ __forceinline__ void mma16816(float* c, const uint32_t* a, const uint32_t* b) {
    asm volatile(
        "mma.sync.aligned.m16n8k16.row.col.f32.f16.f16.f32 "
        "{%0,%1,%2,%3}, {%4,%5,%6,%7}, {%8,%9}, {%0,%1,%2,%3};"
        : "+f"(c[0]), "+f"(c[1]), "+f"(c[2]), "+f"(c[3])
        : "r"(a[0]), "r"(a[1]), "r"(a[2]), "r"(a[3]), "r"(b[0]), "r"(b[1]));
}

// ---------------- prep_w: W -> fp16 A-fragments (L2-hot, tiny) ----------------
// Layout per (s,ks): [m16 0..19][k16 0..1][lane]*16B contiguous.
__global__ __launch_bounds__(256) void prep_w(const float* __restrict__ W) {
    const int ks = blockIdx.x;          // 0..8
    const int mg = blockIdx.y;          // 0..3  (5 m16 each)
    const int s  = blockIdx.z;          // 0..7
    const float* ws = W + (size_t)s * D1 * C_MAX;
    uint4* wd = (uint4*)(g_Wh + ((size_t)s * NSTAGE + ks) * WSTAGE_B);

    const int tid = threadIdx.x;
    #pragma unroll
    for (int it = 0; it < 2; it++) {
        const int j = tid + it * 256;          // 0..319 (tail inactive)
        if (j >= 320) break;
        const int lane = j & 31;
        const int k16  = (j >> 5) & 1;
        const int m16  = mg * 5 + (j >> 6);    // 0..19
        const int g    = lane >> 2;
        const int k0   = ks * 32 + k16 * 16 + (lane & 3) * 2;
        const int mA   = m16 * 16 + g;

        uint32_t r[4];
        #pragma unroll
        for (int rr = 0; rr < 4; rr++) {
            const int m = mA + (rr & 1) * 8;
            const int k = k0 + (rr >> 1) * 8;
            float v0 = (k     < C_MAX) ? ws[(size_t)m * C_MAX + k    ] : 0.0f;
            float v1 = (k + 1 < C_MAX) ? ws[(size_t)m * C_MAX + k + 1] : 0.0f;
            r[rr] = pack_h2(v0, v1);
        }
        uint4 o; o.x = r[0]; o.y = r[1]; o.z = r[2]; o.w = r[3];
        wd[(size_t)(m16 * 2 + k16) * 32 + lane] = o;
    }
}

// ---------------- Fused GEMM ----------------
// Smem: Bfrag 9*8192 = 73728, then 2 slabs of 32x132 f32 (16896 each).
#define BFRAG_SZ  (NSTAGE * 8192)
#define SLAB_SZ   16896
#define GEMM_SMEM (BFRAG_SZ + 2 * SLAB_SZ)    // 107520

template <int MCNT>
__device__ __forceinline__ void gemm_pass(
    uint32_t bfrag, const unsigned char* srcA, int m16base,
    float* __restrict__ orow0, int lane, int wid)
{
    constexpr int MW  = MCNT / 2;     // m-warp groups
    constexpr int NW  = 8 / MW;       // n-warp groups
    constexpr int N8W = 16 / NW;      // n8 per warp
    const int wm = wid % MW;
    const int wn = wid / MW;

    float acc[2][N8W][4];
    #pragma unroll
    for (int i = 0; i < 2; i++)
        #pragma unroll
        for (int j = 0; j < N8W; j++)
            #pragma unroll
            for (int q = 0; q < 4; q++) acc[i][j][q] = 0.0f;

    #pragma unroll 1
    for (int ks = 0; ks < NSTAGE; ks++) {
        const unsigned char* aS = srcA + (size_t)ks * WSTAGE_B;
        #pragma unroll
        for (int k16 = 0; k16 < 2; k16++) {
            if (k16 == 1 && ks == NSTAGE - 1) break;   // K=272

            uint32_t afr[2][4];
            #pragma unroll
            for (int mi = 0; mi < 2; mi++)
                ldg128(afr[mi], aS + (size_t)(m16base + 2 * wm + mi) * 1024
                                   + k16 * 512 + lane * 16);

            uint32_t bfr[N8W][2];
            #pragma unroll
            for (int ni = 0; ni < N8W; ni++)
                lds64(bfr[ni], bfrag + (uint32_t)(ks * 8192 + k16 * 4096
                                   + (wn * N8W + ni) * 256) + lane * 8);

            #pragma unroll
            for (int mi = 0; mi < 2; mi++)
                #pragma unroll
                for (int ni = 0; ni < N8W; ni++)
                    mma16816(acc[mi][ni], afr[mi], bfr[ni]);
        }
    }

    // epilogue
    const int g  = lane >> 2;
    const int c2 = (lane & 3) * 2;
    const int col0 = wn * (N8W * 8) + c2;
    #pragma unroll
    for (int mi = 0; mi < 2; mi++) {
        const int row = m16base * 16 + wm * 32 + mi * 16 + g;
        float* o0 = orow0 + (size_t)row * T_LEN + col0;
        float* o1 = orow0 + (size_t)(row + 8) * T_LEN + col0;
        #pragma unroll
        for (int ni = 0; ni < N8W; ni++) {
            float2 v0; v0.x = acc[mi][ni][0]; v0.y = acc[mi][ni][1];
            float2 v1; v1.x = acc[mi][ni][2]; v1.y = acc[mi][ni][3];
            *(float2*)(o0 + ni * 8) = v0;
            *(float2*)(o1 + ni * 8) = v1;
        }
    }
}

__global__ __launch_bounds__(256, 2) void gemm_fused(const float* __restrict__ X,
                                                     const int* __restrict__ subj,
                                                     float* __restrict__ out) {
    extern __shared__ unsigned char dsm[];
    const uint32_t sbase = smem_u32(dsm);
    const uint32_t bfrag = sbase;

    const int tid  = threadIdx.x;
    const int lane = tid & 31;
    const int wid  = tid >> 5;
    const int nt = blockIdx.x, b = blockIdx.z;
    const int s  = subj[b];

    const float* xb = X + (size_t)b * C_MAX * T_LEN + (size_t)nt * 128;

    // ---- Phase 1: convert X [272 x 128] slice -> fp16 B fragments in smem ----
    float* slab[2] = { (float*)(dsm + BFRAG_SZ), (float*)(dsm + BFRAG_SZ + SLAB_SZ) };

    auto load_slab = [&](int ks) {
        const uint32_t d = sbase + BFRAG_SZ + (uint32_t)(ks & 1) * SLAB_SZ;
        const int c0 = ks * 32;
        #pragma unroll
        for (int it = 0; it < 4; it++) {
            const int idx = tid + it * 256;        // 0..1023
            const int cl  = idx >> 5;
            const int t4  = (idx & 31) * 4;
            const int ok  = (c0 + cl < C_MAX) ? 16 : 0;
            cp16p(d + (uint32_t)(cl * 132 + t4) * 4,
                  xb + (size_t)(c0 + cl) * T_LEN + t4, ok);
        }
    };

    load_slab(0); CP_COMMIT();
    #pragma unroll 1
    for (int ks = 0; ks < NSTAGE; ks++) {
        if (ks + 1 < NSTAGE) { load_slab(ks + 1); CP_COMMIT(); CP_WAIT(1); }
        else                 { CP_WAIT(0); }
        __syncthreads();

        const float* sl = slab[ks & 1];
        #pragma unroll
        for (int it = 0; it < 4; it++) {
            const int j    = tid + it * 256;       // 0..1023
            const int ln   = j & 31;
            const int n8   = (j >> 5) & 15;
            const int k16  = j >> 9;
            const int t    = n8 * 8 + (ln >> 2);
            const int kc   = k16 * 16 + (ln & 3) * 2;
            uint32_t v0 = pack_h2(sl[kc * 132 + t],       sl[(kc + 1) * 132 + t]);
            uint32_t v1 = pack_h2(sl[(kc + 8) * 132 + t], sl[(kc + 9) * 132 + t]);
            sts64(bfrag + (uint32_t)(ks * 8192) + (uint32_t)j * 8, v0, v1);
        }
        __syncthreads();
    }

    // ---- Phase 2: three m-passes against resident B (sync-free) ----
    const unsigned char* srcA = g_Wh + (size_t)s * NSTAGE * WSTAGE_B;
    float* orow0 = out + (size_t)b * D1 * T_LEN + nt * 128;

    gemm_pass<8>(bfrag, srcA, 0,  orow0, lane, wid);   // rows   0..127
    gemm_pass<8>(bfrag, srcA, 8,  orow0, lane, wid);   // rows 128..255
    gemm_pass<4>(bfrag, srcA, 16, orow0, lane, wid);   // rows 256..319
}

// ---------------- Host launcher ----------------
extern "C" void kernel_launch(void* const* d_in, const int* in_sizes, int n_in,
                              void* d_out, int out_size) {
    const float* X    = (const float*)d_in[0];  // [128, 272, 512]
    const int*   subj = (const int*)  d_in[1];  // [128]
    const float* W    = (const float*)d_in[2];  // [8, 320, 272]
    float*       out  = (float*)d_out;          // [128, 320, 512]

    cudaFuncSetAttribute(gemm_fused, cudaFuncAttributeMaxDynamicSharedMemorySize, GEMM_SMEM);

    prep_w<<<dim3(NSTAGE, 4, 8), 256>>>(W);
    gemm_fused<<<dim3(NTILES, 1, B_SZ), 256, GEMM_SMEM>>>(X, subj, out);
}